// round 2
// baseline (speedup 1.0000x reference)
#include <cuda_runtime.h>
#include <cuda_bf16.h>
#include <math.h>

#define T  8192
#define E  20
#define H1 30
#define H2 50
#define HL 300
#define NT 50
#define G1 (4*H1)   // 120
#define G2 (4*H2)   // 200
#define D2 (2*H1)   // 60
#define D3 (2*H2)   // 100

// ---- scratch (no allocations allowed) ----
__device__ float g_gx_fw1[T*G1];
__device__ float g_gx_bw1[T*G1];
__device__ float g_l1[T*D2];
__device__ float g_gx_fw2[T*G2];
__device__ float g_gx_bw2[T*G2];
__device__ float g_l2[T*D3];

__device__ __forceinline__ float sigf(float x) { return 1.0f / (1.0f + expf(-x)); }

// ============================================================
// Kernel 1: embedding gather + layer-1 input projections.
// Block t computes gx_fw1[t] from e[t] and gx_bw1[T-1-t] from e[t]
// (the bw LSTM consumes the reversed sequence).
// ============================================================
__global__ void k_gx1(const int* __restrict__ x, const float* __restrict__ emb,
                      const float* __restrict__ WihF, const float* __restrict__ bF,
                      const float* __restrict__ WihB, const float* __restrict__ bB) {
    __shared__ float e[E];
    int t = blockIdx.x;
    int j = threadIdx.x;
    if (j < E) e[j] = emb[(size_t)x[t] * E + j];
    __syncthreads();
    if (j < G1) {
        float aF = bF[j], aB = bB[j];
        #pragma unroll
        for (int k = 0; k < E; k++) {
            float ev = e[k];
            aF += WihF[j*E + k] * ev;
            aB += WihB[j*E + k] * ev;
        }
        g_gx_fw1[t*G1 + j] = aF;
        g_gx_bw1[(T-1-t)*G1 + j] = aB;
    }
}

// ============================================================
// Kernel 2: layer-1 scans (fw1 + bw1), one warp per cell.
// H1=30 <= 32: h,c live in lanes; Whh@h via shuffles, no smem,
// no barriers. gx double-buffered one step ahead.
// ============================================================
__global__ void __launch_bounds__(32, 1) k_scan1(
    const float* __restrict__ WhhF, const float* __restrict__ h0F, const float* __restrict__ c0F,
    const float* __restrict__ WhhB, const float* __restrict__ h0B, const float* __restrict__ c0B) {
    const bool bw = (blockIdx.x == 1);
    const float* Whh = bw ? WhhB : WhhF;
    const float* h0  = bw ? h0B  : h0F;
    const float* c0  = bw ? c0B  : c0F;
    const float* gx  = bw ? g_gx_bw1 : g_gx_fw1;
    const int off = bw ? H1 : 0;

    int j = threadIdx.x;
    bool act = (j < H1);
    int jj = act ? j : 0;

    float wi[H1], wf[H1], wg[H1], wo[H1];
    #pragma unroll
    for (int k = 0; k < H1; k++) {
        wi[k] = act ? Whh[(j        )*H1 + k] : 0.f;
        wf[k] = act ? Whh[(j +   H1)*H1 + k] : 0.f;
        wg[k] = act ? Whh[(j + 2*H1)*H1 + k] : 0.f;
        wo[k] = act ? Whh[(j + 3*H1)*H1 + k] : 0.f;
    }
    float h = act ? h0[j] : 0.f;
    float c = act ? c0[j] : 0.f;

    float gi = gx[jj], gf = gx[H1 + jj], gg = gx[2*H1 + jj], go = gx[3*H1 + jj];

    for (int t = 0; t < T; t++) {
        // prefetch next step's input projections (hides L2 latency)
        float ni = 0.f, nf = 0.f, ng = 0.f, no = 0.f;
        if (t + 1 < T) {
            const float* p = gx + (size_t)(t+1)*G1;
            ni = p[jj]; nf = p[H1 + jj]; ng = p[2*H1 + jj]; no = p[3*H1 + jj];
        }
        float ai0 = gi, ai1 = 0.f, af0 = gf, af1 = 0.f;
        float ag0 = gg, ag1 = 0.f, ao0 = go, ao1 = 0.f;
        #pragma unroll
        for (int k = 0; k < H1; k += 2) {
            float hk0 = __shfl_sync(0xFFFFFFFFu, h, k);
            float hk1 = __shfl_sync(0xFFFFFFFFu, h, k + 1);
            ai0 += wi[k]*hk0;  ai1 += wi[k+1]*hk1;
            af0 += wf[k]*hk0;  af1 += wf[k+1]*hk1;
            ag0 += wg[k]*hk0;  ag1 += wg[k+1]*hk1;
            ao0 += wo[k]*hk0;  ao1 += wo[k+1]*hk1;
        }
        float I  = sigf(ai0 + ai1);
        float F  = sigf(af0 + af1);
        float Gv = tanhf(ag0 + ag1);
        float O  = sigf(ao0 + ao1);
        c = F * c + I * Gv;
        h = O * tanhf(c);
        if (act) g_l1[(size_t)t*D2 + off + j] = h;
        gi = ni; gf = nf; gg = ng; go = no;
    }
}

// ============================================================
// Kernel 3: layer-2 input projections. Wih stored TRANSPOSED in
// shared as [D2][G2] so thread j reads W[k*G2+j]: consecutive
// threads -> consecutive banks, zero conflicts, zero padding.
// Shared = 200*60*4 + 240 = 48.2 KB (under 48KB static? no:
// 48,240 B < 49,152 B limit). Each block handles a contiguous
// chunk of t for one cell (blockIdx.y).
// ============================================================
#define GX2_BLOCKS 64
__global__ void __launch_bounds__(256) k_gx2(
    const float* __restrict__ WihF, const float* __restrict__ bF,
    const float* __restrict__ WihB, const float* __restrict__ bB) {
    __shared__ float W[D2 * G2];   // [k][j] layout
    __shared__ float row[D2];
    const bool bw = (blockIdx.y == 1);
    const float* Wih = bw ? WihB : WihF;
    const float* b   = bw ? bB   : bF;
    float* dst = bw ? g_gx_bw2 : g_gx_fw2;

    // transpose-load: Wih is [G2][D2] row-major -> W[k*G2 + r]
    for (int i = threadIdx.x; i < G2*D2; i += blockDim.x) {
        int r = i / D2, k = i % D2;
        W[k*G2 + r] = Wih[i];
    }
    float bias = (threadIdx.x < G2) ? b[threadIdx.x] : 0.f;
    __syncthreads();

    const int tpb = T / GX2_BLOCKS;
    const int t0 = blockIdx.x * tpb;
    for (int t = t0; t < t0 + tpb; t++) {
        int src = bw ? (T-1-t) : t;
        __syncthreads();
        for (int i = threadIdx.x; i < D2; i += blockDim.x) row[i] = g_l1[(size_t)src*D2 + i];
        __syncthreads();
        if (threadIdx.x < G2) {
            float acc = bias;
            #pragma unroll
            for (int k = 0; k < D2; k++) acc += W[k*G2 + threadIdx.x] * row[k];
            dst[(size_t)t*G2 + threadIdx.x] = acc;
        }
    }
}

// ============================================================
// Kernel 4: layer-2 scans (fw2 + bw2). 200 threads each own one
// gate row of Whh in registers; h broadcast from shared (float4);
// activated gates exchanged via shared; 2 barriers/step.
// ============================================================
__global__ void __launch_bounds__(256, 1) k_scan2(
    const float* __restrict__ WhhF, const float* __restrict__ h0F, const float* __restrict__ c0F,
    const float* __restrict__ WhhB, const float* __restrict__ h0B, const float* __restrict__ c0B) {
    const bool bw = (blockIdx.x == 1);
    const float* Whh = bw ? WhhB : WhhF;
    const float* h0  = bw ? h0B  : h0F;
    const float* c0  = bw ? c0B  : c0F;
    const float* gx  = bw ? g_gx_bw2 : g_gx_fw2;
    const int off = bw ? H2 : 0;

    __shared__ __align__(16) float h_sh[52];
    __shared__ float act_sh[G2];

    int j = threadIdx.x;
    float w[52];
    #pragma unroll
    for (int k = 0; k < 52; k++) w[k] = 0.f;
    if (j < G2) {
        #pragma unroll
        for (int k = 0; k < H2; k++) w[k] = Whh[j*H2 + k];
    }
    if (j < H2) h_sh[j] = h0[j];
    if (j >= H2 && j < 52) h_sh[j] = 0.f;
    float c = (j < H2) ? c0[j] : 0.f;
    int gate = j / H2;   // 0:i 1:f 2:g 3:o for j<200

    float gcur = (j < G2) ? gx[j] : 0.f;
    __syncthreads();

    for (int t = 0; t < T; t++) {
        float gnext = 0.f;
        if (j < G2 && t + 1 < T) gnext = gx[(size_t)(t+1)*G2 + j];

        float a0 = gcur, a1 = 0.f, a2 = 0.f, a3 = 0.f;
        const float4* h4 = (const float4*)h_sh;
        #pragma unroll
        for (int k4 = 0; k4 < 13; k4++) {
            float4 hv = h4[k4];
            a0 += w[4*k4 + 0] * hv.x;
            a1 += w[4*k4 + 1] * hv.y;
            a2 += w[4*k4 + 2] * hv.z;
            a3 += w[4*k4 + 3] * hv.w;
        }
        float acc = (a0 + a1) + (a2 + a3);
        float a = (gate == 2) ? tanhf(acc) : sigf(acc);
        if (j < G2) act_sh[j] = a;
        __syncthreads();

        if (j < H2) {
            float I  = act_sh[j];
            float F  = act_sh[j +   H2];
            float Gv = act_sh[j + 2*H2];
            float O  = act_sh[j + 3*H2];
            c = F * c + I * Gv;
            float hn = O * tanhf(c);
            h_sh[j] = hn;
            g_l2[(size_t)t*D3 + off + j] = hn;
        }
        gcur = gnext;
        __syncthreads();
    }
}

// ============================================================
// Kernel 5: final MLP. Both weight matrices live in dynamic
// shared (182 KB, 1 block/SM), float4 conflict-free dots.
// ============================================================
#define MLP_SMEM ((HL*D3 + NT*HL + D3 + HL) * 4)
__global__ void __launch_bounds__(320, 1) k_mlp(
    const float* __restrict__ W1, const float* __restrict__ b1,
    const float* __restrict__ W2, const float* __restrict__ b2,
    float* __restrict__ out) {
    extern __shared__ float sm[];
    float* W1s  = sm;                 // HL*D3 = 30000
    float* W2s  = W1s + HL*D3;        // NT*HL = 15000
    float* rowS = W2s + NT*HL;        // D3 = 100
    float* hidS = rowS + D3;          // HL = 300

    int tid = threadIdx.x;
    for (int i = tid; i < HL*D3; i += blockDim.x) W1s[i] = W1[i];
    for (int i = tid; i < NT*HL; i += blockDim.x) W2s[i] = W2[i];
    __syncthreads();

    for (int t = blockIdx.x; t < T; t += gridDim.x) {
        if (tid < D3) rowS[tid] = g_l2[(size_t)t*D3 + tid];
        __syncthreads();
        if (tid < HL) {
            float acc = b1[tid];
            const float4* wr = (const float4*)(W1s + tid*D3);
            const float4* r4 = (const float4*)rowS;
            #pragma unroll
            for (int k = 0; k < D3/4; k++) {
                float4 wv = wr[k]; float4 rv = r4[k];
                acc += wv.x*rv.x + wv.y*rv.y + wv.z*rv.z + wv.w*rv.w;
            }
            hidS[tid] = tanhf(acc);
        }
        __syncthreads();
        if (tid < NT) {
            float acc = b2[tid];
            const float4* wr = (const float4*)(W2s + tid*HL);
            const float4* h4 = (const float4*)hidS;
            #pragma unroll
            for (int k = 0; k < HL/4; k++) {
                float4 wv = wr[k]; float4 hv = h4[k];
                acc += wv.x*hv.x + wv.y*hv.y + wv.z*hv.z + wv.w*hv.w;
            }
            out[(size_t)t*NT + tid] = acc;
        }
        __syncthreads();
    }
}

// ============================================================
// launch
// ============================================================
extern "C" void kernel_launch(void* const* d_in, const int* in_sizes, int n_in,
                              void* d_out, int out_size) {
    const int*   x   = (const int*)  d_in[0];
    const float* emb = (const float*)d_in[1];

    const float* fw1_Wih = (const float*)d_in[2];
    const float* fw1_Whh = (const float*)d_in[3];
    const float* fw1_b   = (const float*)d_in[4];
    const float* fw1_h0  = (const float*)d_in[5];
    const float* fw1_c0  = (const float*)d_in[6];

    const float* bw1_Wih = (const float*)d_in[7];
    const float* bw1_Whh = (const float*)d_in[8];
    const float* bw1_b   = (const float*)d_in[9];
    const float* bw1_h0  = (const float*)d_in[10];
    const float* bw1_c0  = (const float*)d_in[11];

    const float* fw2_Wih = (const float*)d_in[12];
    const float* fw2_Whh = (const float*)d_in[13];
    const float* fw2_b   = (const float*)d_in[14];
    const float* fw2_h0  = (const float*)d_in[15];
    const float* fw2_c0  = (const float*)d_in[16];

    const float* bw2_Wih = (const float*)d_in[17];
    const float* bw2_Whh = (const float*)d_in[18];
    const float* bw2_b   = (const float*)d_in[19];
    const float* bw2_h0  = (const float*)d_in[20];
    const float* bw2_c0  = (const float*)d_in[21];

    const float* lin1_W = (const float*)d_in[22];
    const float* lin1_b = (const float*)d_in[23];
    const float* lin2_W = (const float*)d_in[24];
    const float* lin2_b = (const float*)d_in[25];

    static bool smem_set = false;
    cudaFuncSetAttribute(k_mlp, cudaFuncAttributeMaxDynamicSharedMemorySize, MLP_SMEM);

    k_gx1<<<T, 128>>>(x, emb, fw1_Wih, fw1_b, bw1_Wih, bw1_b);
    k_scan1<<<2, 32>>>(fw1_Whh, fw1_h0, fw1_c0, bw1_Whh, bw1_h0, bw1_c0);
    k_gx2<<<dim3(GX2_BLOCKS, 2), 256>>>(fw2_Wih, fw2_b, bw2_Wih, bw2_b);
    k_scan2<<<2, 256>>>(fw2_Whh, fw2_h0, fw2_c0, bw2_Whh, bw2_h0, bw2_c0);
    k_mlp<<<148, 320, MLP_SMEM>>>(lin1_W, lin1_b, lin2_W, lin2_b, (float*)d_out);
    (void)smem_set;
}

// round 3
// speedup vs baseline: 1.3866x; 1.3866x over previous
#include <cuda_runtime.h>
#include <cuda_bf16.h>
#include <math.h>

#define T  8192
#define E  20
#define H1 30
#define H2 50
#define HL 300
#define NT 50
#define G1 (4*H1)   // 120
#define G2 (4*H2)   // 200
#define D2 (2*H1)   // 60
#define D3 (2*H2)   // 100

// ---- scratch (no allocations allowed) ----
__device__ float g_gx_fw1[T*G1];
__device__ float g_gx_bw1[T*G1];
__device__ float g_l1[T*D2];
__device__ float g_gx_fw2[T*G2];
__device__ float g_gx_bw2[T*G2];
__device__ float g_l2[T*D3];

typedef unsigned long long u64;

// ---- packed f32x2 + fast-activation helpers ----
__device__ __forceinline__ u64 pk(float lo, float hi) {
    u64 r; asm("mov.b64 %0, {%1, %2};" : "=l"(r) : "f"(lo), "f"(hi)); return r;
}
__device__ __forceinline__ void upk(u64 v, float& lo, float& hi) {
    asm("mov.b64 {%0, %1}, %2;" : "=f"(lo), "=f"(hi) : "l"(v));
}
__device__ __forceinline__ u64 ffma2(u64 a, u64 b, u64 c) {
    u64 d; asm("fma.rn.f32x2 %0, %1, %2, %3;" : "=l"(d) : "l"(a), "l"(b), "l"(c)); return d;
}
__device__ __forceinline__ float tanh_ap(float x) {
    float y; asm("tanh.approx.f32 %0, %1;" : "=f"(y) : "f"(x)); return y;
}

// ============================================================
// Kernel 1: embedding gather + layer-1 input projections.
// ============================================================
__global__ void k_gx1(const int* __restrict__ x, const float* __restrict__ emb,
                      const float* __restrict__ WihF, const float* __restrict__ bF,
                      const float* __restrict__ WihB, const float* __restrict__ bB) {
    __shared__ float e[E];
    int t = blockIdx.x;
    int j = threadIdx.x;
    if (j < E) e[j] = emb[(size_t)x[t] * E + j];
    __syncthreads();
    if (j < G1) {
        float aF = bF[j], aB = bB[j];
        #pragma unroll
        for (int k = 0; k < E; k++) {
            float ev = e[k];
            aF += WihF[j*E + k] * ev;
            aB += WihB[j*E + k] * ev;
        }
        g_gx_fw1[t*G1 + j] = aF;
        g_gx_bw1[(T-1-t)*G1 + j] = aB;
    }
}

// ============================================================
// Kernel 2: layer-1 scans. 4 warps per cell: warp = gate, lane = row.
// Packed f32x2 matvec from shared h; tanh.approx activations;
// warp 0 does the c/h update; 2 barriers/step.
// ============================================================
__global__ void __launch_bounds__(128, 1) k_scan1(
    const float* __restrict__ WhhF, const float* __restrict__ h0F, const float* __restrict__ c0F,
    const float* __restrict__ WhhB, const float* __restrict__ h0B, const float* __restrict__ c0B) {
    const bool bw = (blockIdx.x == 1);
    const float* Whh = bw ? WhhB : WhhF;
    const float* h0  = bw ? h0B  : h0F;
    const float* c0  = bw ? c0B  : c0F;
    const float* gx  = bw ? g_gx_bw1 : g_gx_fw1;
    const int off = bw ? H1 : 0;

    __shared__ __align__(16) float h_sh[32];
    __shared__ float act_sh[128];

    const int tid = threadIdx.x;
    const int w = tid >> 5;        // gate 0..3
    const int l = tid & 31;        // row (valid < 30)
    const bool rowok = (l < H1);
    const int row = w * H1 + (rowok ? l : 0);   // [0,120)

    // pre-pack Whh row into f32x2 pairs (padded to 16)
    u64 wp[16];
    #pragma unroll
    for (int k = 0; k < 15; k++) {
        float lo = rowok ? Whh[row*H1 + 2*k]     : 0.f;
        float hi = rowok ? Whh[row*H1 + 2*k + 1] : 0.f;
        wp[k] = pk(lo, hi);
    }
    wp[15] = pk(0.f, 0.f);

    // activation params: a = m*tanh(s*x)+b   (gate g: tanh; else sigmoid)
    const float s = (w == 2) ? 1.f : 0.5f;
    const float m = s;
    const float bc = (w == 2) ? 0.f : 0.5f;

    if (tid < H1) h_sh[tid] = h0[tid];
    if (tid >= H1 && tid < 32) h_sh[tid] = 0.f;
    float c = (w == 0 && rowok) ? c0[l] : 0.f;

    float gcur = rowok ? gx[row] : 0.f;
    __syncthreads();

    for (int t = 0; t < T; t++) {
        float gnext = (rowok && t + 1 < T) ? gx[(size_t)(t+1)*G1 + row] : 0.f;

        const ulonglong2* h8 = (const ulonglong2*)h_sh;
        u64 a0 = pk(gcur, 0.f), a1 = pk(0.f,0.f), a2 = pk(0.f,0.f), a3 = pk(0.f,0.f);
        #pragma unroll
        for (int k = 0; k < 4; k++) {
            ulonglong2 hv = h8[2*k];
            ulonglong2 hw = h8[2*k + 1];
            a0 = ffma2(wp[4*k + 0], hv.x, a0);
            a1 = ffma2(wp[4*k + 1], hv.y, a1);
            a2 = ffma2(wp[4*k + 2], hw.x, a2);
            a3 = ffma2(wp[4*k + 3], hw.y, a3);
        }
        float x0,x1,x2,x3,x4,x5,x6,x7;
        upk(a0,x0,x1); upk(a1,x2,x3); upk(a2,x4,x5); upk(a3,x6,x7);
        float acc = ((x0+x1)+(x2+x3)) + ((x4+x5)+(x6+x7));
        act_sh[tid] = fmaf(m, tanh_ap(s*acc), bc);
        __syncthreads();

        if (w == 0 && rowok) {
            float I  = act_sh[l];
            float F  = act_sh[32 + l];
            float Gv = act_sh[64 + l];
            float O  = act_sh[96 + l];
            c = F * c + I * Gv;
            float hn = O * tanh_ap(c);
            h_sh[l] = hn;
            g_l1[(size_t)t*D2 + off + l] = hn;
        }
        gcur = gnext;
        __syncthreads();
    }
}

// ============================================================
// Kernel 3: layer-2 input projections (transposed W in shared).
// ============================================================
#define GX2_BLOCKS 64
__global__ void __launch_bounds__(256) k_gx2(
    const float* __restrict__ WihF, const float* __restrict__ bF,
    const float* __restrict__ WihB, const float* __restrict__ bB) {
    __shared__ float W[D2 * G2];   // [k][j]
    __shared__ float row[D2];
    const bool bw = (blockIdx.y == 1);
    const float* Wih = bw ? WihB : WihF;
    const float* b   = bw ? bB   : bF;
    float* dst = bw ? g_gx_bw2 : g_gx_fw2;

    for (int i = threadIdx.x; i < G2*D2; i += blockDim.x) {
        int r = i / D2, k = i % D2;
        W[k*G2 + r] = Wih[i];
    }
    float bias = (threadIdx.x < G2) ? b[threadIdx.x] : 0.f;
    __syncthreads();

    const int tpb = T / GX2_BLOCKS;
    const int t0 = blockIdx.x * tpb;
    for (int t = t0; t < t0 + tpb; t++) {
        int src = bw ? (T-1-t) : t;
        __syncthreads();
        for (int i = threadIdx.x; i < D2; i += blockDim.x) row[i] = g_l1[(size_t)src*D2 + i];
        __syncthreads();
        if (threadIdx.x < G2) {
            float acc = bias;
            #pragma unroll
            for (int k = 0; k < D2; k++) acc += W[k*G2 + threadIdx.x] * row[k];
            dst[(size_t)t*G2 + threadIdx.x] = acc;
        }
    }
}

// ============================================================
// Kernel 4: layer-2 scans. 200 active threads (thread = gate row),
// packed f32x2 matvec, tanh.approx activations, 2 barriers/step.
// ============================================================
__global__ void __launch_bounds__(256, 1) k_scan2(
    const float* __restrict__ WhhF, const float* __restrict__ h0F, const float* __restrict__ c0F,
    const float* __restrict__ WhhB, const float* __restrict__ h0B, const float* __restrict__ c0B) {
    const bool bw = (blockIdx.x == 1);
    const float* Whh = bw ? WhhB : WhhF;
    const float* h0  = bw ? h0B  : h0F;
    const float* c0  = bw ? c0B  : c0F;
    const float* gx  = bw ? g_gx_bw2 : g_gx_fw2;
    const int off = bw ? H2 : 0;

    __shared__ __align__(16) float h_sh[52];
    __shared__ float act_sh[G2];

    const int j = threadIdx.x;
    const bool rowok = (j < G2);
    const int gate = rowok ? (j / H2) : 0;

    // pre-pack Whh row (50 floats -> 25 pairs, padded to 26)
    u64 wp[26];
    #pragma unroll
    for (int k = 0; k < 25; k++) {
        float lo = rowok ? Whh[j*H2 + 2*k]     : 0.f;
        float hi = rowok ? Whh[j*H2 + 2*k + 1] : 0.f;
        wp[k] = pk(lo, hi);
    }
    wp[25] = pk(0.f, 0.f);

    const float s = (gate == 2) ? 1.f : 0.5f;
    const float m = s;
    const float bc = (gate == 2) ? 0.f : 0.5f;

    if (j < H2) h_sh[j] = h0[j];
    if (j >= H2 && j < 52) h_sh[j] = 0.f;
    float c = (j < H2) ? c0[j] : 0.f;

    float gcur = rowok ? gx[j] : 0.f;
    __syncthreads();

    for (int t = 0; t < T; t++) {
        float gnext = (rowok && t + 1 < T) ? gx[(size_t)(t+1)*G2 + j] : 0.f;

        const ulonglong2* h8 = (const ulonglong2*)h_sh;
        u64 a0 = pk(gcur, 0.f), a1 = pk(0.f,0.f), a2 = pk(0.f,0.f), a3 = pk(0.f,0.f);
        #pragma unroll
        for (int k = 0; k < 13; k++) {
            ulonglong2 hv = h8[k];
            if (k & 1) {
                a2 = ffma2(wp[2*k],     hv.x, a2);
                a3 = ffma2(wp[2*k + 1], hv.y, a3);
            } else {
                a0 = ffma2(wp[2*k],     hv.x, a0);
                a1 = ffma2(wp[2*k + 1], hv.y, a1);
            }
        }
        float x0,x1,x2,x3,x4,x5,x6,x7;
        upk(a0,x0,x1); upk(a1,x2,x3); upk(a2,x4,x5); upk(a3,x6,x7);
        float acc = ((x0+x1)+(x2+x3)) + ((x4+x5)+(x6+x7));
        if (rowok) act_sh[j] = fmaf(m, tanh_ap(s*acc), bc);
        __syncthreads();

        if (j < H2) {
            float I  = act_sh[j];
            float F  = act_sh[H2 + j];
            float Gv = act_sh[2*H2 + j];
            float O  = act_sh[3*H2 + j];
            c = F * c + I * Gv;
            float hn = O * tanh_ap(c);
            h_sh[j] = hn;
            g_l2[(size_t)t*D3 + off + j] = hn;
        }
        gcur = gnext;
        __syncthreads();
    }
}

// ============================================================
// Kernel 5: final MLP (weights in dynamic shared).
// ============================================================
#define MLP_SMEM ((HL*D3 + NT*HL + D3 + HL) * 4)
__global__ void __launch_bounds__(320, 1) k_mlp(
    const float* __restrict__ W1, const float* __restrict__ b1,
    const float* __restrict__ W2, const float* __restrict__ b2,
    float* __restrict__ out) {
    extern __shared__ float sm[];
    float* W1s  = sm;
    float* W2s  = W1s + HL*D3;
    float* rowS = W2s + NT*HL;
    float* hidS = rowS + D3;

    int tid = threadIdx.x;
    for (int i = tid; i < HL*D3; i += blockDim.x) W1s[i] = W1[i];
    for (int i = tid; i < NT*HL; i += blockDim.x) W2s[i] = W2[i];
    __syncthreads();

    for (int t = blockIdx.x; t < T; t += gridDim.x) {
        if (tid < D3) rowS[tid] = g_l2[(size_t)t*D3 + tid];
        __syncthreads();
        if (tid < HL) {
            float acc = b1[tid];
            const float4* wr = (const float4*)(W1s + tid*D3);
            const float4* r4 = (const float4*)rowS;
            #pragma unroll
            for (int k = 0; k < D3/4; k++) {
                float4 wv = wr[k]; float4 rv = r4[k];
                acc += wv.x*rv.x + wv.y*rv.y + wv.z*rv.z + wv.w*rv.w;
            }
            hidS[tid] = tanhf(acc);
        }
        __syncthreads();
        if (tid < NT) {
            float acc = b2[tid];
            const float4* wr = (const float4*)(W2s + tid*HL);
            const float4* h4 = (const float4*)hidS;
            #pragma unroll
            for (int k = 0; k < HL/4; k++) {
                float4 wv = wr[k]; float4 hv = h4[k];
                acc += wv.x*hv.x + wv.y*hv.y + wv.z*hv.z + wv.w*hv.w;
            }
            out[(size_t)t*NT + tid] = acc;
        }
        __syncthreads();
    }
}

// ============================================================
// launch
// ============================================================
extern "C" void kernel_launch(void* const* d_in, const int* in_sizes, int n_in,
                              void* d_out, int out_size) {
    const int*   x   = (const int*)  d_in[0];
    const float* emb = (const float*)d_in[1];

    const float* fw1_Wih = (const float*)d_in[2];
    const float* fw1_Whh = (const float*)d_in[3];
    const float* fw1_b   = (const float*)d_in[4];
    const float* fw1_h0  = (const float*)d_in[5];
    const float* fw1_c0  = (const float*)d_in[6];

    const float* bw1_Wih = (const float*)d_in[7];
    const float* bw1_Whh = (const float*)d_in[8];
    const float* bw1_b   = (const float*)d_in[9];
    const float* bw1_h0  = (const float*)d_in[10];
    const float* bw1_c0  = (const float*)d_in[11];

    const float* fw2_Wih = (const float*)d_in[12];
    const float* fw2_Whh = (const float*)d_in[13];
    const float* fw2_b   = (const float*)d_in[14];
    const float* fw2_h0  = (const float*)d_in[15];
    const float* fw2_c0  = (const float*)d_in[16];

    const float* bw2_Wih = (const float*)d_in[17];
    const float* bw2_Whh = (const float*)d_in[18];
    const float* bw2_b   = (const float*)d_in[19];
    const float* bw2_h0  = (const float*)d_in[20];
    const float* bw2_c0  = (const float*)d_in[21];

    const float* lin1_W = (const float*)d_in[22];
    const float* lin1_b = (const float*)d_in[23];
    const float* lin2_W = (const float*)d_in[24];
    const float* lin2_b = (const float*)d_in[25];

    cudaFuncSetAttribute(k_mlp, cudaFuncAttributeMaxDynamicSharedMemorySize, MLP_SMEM);

    k_gx1<<<T, 128>>>(x, emb, fw1_Wih, fw1_b, bw1_Wih, bw1_b);
    k_scan1<<<2, 128>>>(fw1_Whh, fw1_h0, fw1_c0, bw1_Whh, bw1_h0, bw1_c0);
    k_gx2<<<dim3(GX2_BLOCKS, 2), 256>>>(fw2_Wih, fw2_b, bw2_Wih, bw2_b);
    k_scan2<<<2, 256>>>(fw2_Whh, fw2_h0, fw2_c0, bw2_Whh, bw2_h0, bw2_c0);
    k_mlp<<<148, 320, MLP_SMEM>>>(lin1_W, lin1_b, lin2_W, lin2_b, (float*)d_out);
}

// round 5
// speedup vs baseline: 1.7659x; 1.2736x over previous
#include <cuda_runtime.h>
#include <cuda_bf16.h>
#include <math.h>

#define T  8192
#define E  20
#define H1 30
#define H2 50
#define HL 300
#define NT 50
#define G1 (4*H1)   // 120
#define G2 (4*H2)   // 200
#define D2 (2*H1)   // 60
#define D3 (2*H2)   // 100

// ---- scratch (no allocations allowed) ----
__device__ float g_gx_fw1[T*G1];
__device__ float g_gx_bw1[T*G1];
__device__ float g_l1[T*D2];
__device__ float g_gx_fw2[T*G2];
__device__ float g_gx_bw2[T*G2];
__device__ float g_l2[T*D3];

typedef unsigned long long u64;

// ---- packed f32x2 + fast-activation helpers ----
__device__ __forceinline__ u64 pk(float lo, float hi) {
    u64 r; asm("mov.b64 %0, {%1, %2};" : "=l"(r) : "f"(lo), "f"(hi)); return r;
}
__device__ __forceinline__ void upk(u64 v, float& lo, float& hi) {
    asm("mov.b64 {%0, %1}, %2;" : "=f"(lo), "=f"(hi) : "l"(v));
}
__device__ __forceinline__ u64 ffma2(u64 a, u64 b, u64 c) {
    u64 d; asm("fma.rn.f32x2 %0, %1, %2, %3;" : "=l"(d) : "l"(a), "l"(b), "l"(c)); return d;
}
__device__ __forceinline__ float tanh_ap(float x) {
    float y; asm("tanh.approx.f32 %0, %1;" : "=f"(y) : "f"(x)); return y;
}

// ============================================================
// Kernel 1: embedding gather + layer-1 input projections.
// ============================================================
__global__ void k_gx1(const int* __restrict__ x, const float* __restrict__ emb,
                      const float* __restrict__ WihF, const float* __restrict__ bF,
                      const float* __restrict__ WihB, const float* __restrict__ bB) {
    __shared__ float e[E];
    int t = blockIdx.x;
    int j = threadIdx.x;
    if (j < E) e[j] = emb[(size_t)x[t] * E + j];
    __syncthreads();
    if (j < G1) {
        float aF = bF[j], aB = bB[j];
        #pragma unroll
        for (int k = 0; k < E; k++) {
            float ev = e[k];
            aF += WihF[j*E + k] * ev;
            aB += WihB[j*E + k] * ev;
        }
        g_gx_fw1[t*G1 + j] = aF;
        g_gx_bw1[(T-1-t)*G1 + j] = aB;
    }
}

// ============================================================
// Kernel 2: layer-1 scan, (unit, gate-pair) layout.
// thread 2u+p: p=0 -> rows {i_u, f_u}; p=1 -> rows {g_u, o_u}.
// Activated gates exchanged by ONE shfl_xor(1); c,h computed
// redundantly in both pair lanes; ping-pong h buffer -> ONE
// __syncthreads per step. gx prefetched 2 steps deep.
// ============================================================
__global__ void __launch_bounds__(64, 1) k_scan1(
    const float* __restrict__ WhhF, const float* __restrict__ h0F, const float* __restrict__ c0F,
    const float* __restrict__ WhhB, const float* __restrict__ h0B, const float* __restrict__ c0B) {
    const bool bw = (blockIdx.x == 1);
    const float* Whh = bw ? WhhB : WhhF;
    const float* h0  = bw ? h0B  : h0F;
    const float* c0  = bw ? c0B  : c0F;
    const float* gx  = bw ? g_gx_bw1 : g_gx_fw1;
    const int off = bw ? H1 : 0;

    __shared__ __align__(16) float h_sh[2][32];

    const int tid = threadIdx.x;
    const int u = tid >> 1;
    const int p = tid & 1;
    const bool valid = (u < H1);
    const int uu = valid ? u : 0;
    const int r0 = p ? (2*H1 + uu) : uu;          // i or g
    const int r1 = p ? (3*H1 + uu) : (H1 + uu);   // f or o

    u64 wp0[16], wp1[16];
    #pragma unroll
    for (int k = 0; k < 15; k++) {
        wp0[k] = pk(valid ? Whh[r0*H1 + 2*k] : 0.f, valid ? Whh[r0*H1 + 2*k + 1] : 0.f);
        wp1[k] = pk(valid ? Whh[r1*H1 + 2*k] : 0.f, valid ? Whh[r1*H1 + 2*k + 1] : 0.f);
    }
    wp0[15] = pk(0.f, 0.f);
    wp1[15] = pk(0.f, 0.f);

    // row0 activation: p=0 -> sigmoid(i), p=1 -> tanh(g). row1 always sigmoid.
    const float s0 = p ? 1.f : 0.5f;
    const float m0 = s0;
    const float b0 = p ? 0.f : 0.5f;

    if (tid < 32) {
        h_sh[0][tid] = (tid < H1) ? h0[tid] : 0.f;
        h_sh[1][tid] = 0.f;
    }
    float c = valid ? c0[uu] : 0.f;

    float g00 = valid ? gx[r0] : 0.f;
    float g01 = valid ? gx[r1] : 0.f;
    float g10 = 0.f, g11 = 0.f;
    if (valid) { const float* pg = gx + G1; g10 = pg[r0]; g11 = pg[r1]; }
    __syncthreads();

    int buf = 0;
    for (int t = 0; t < T; t++) {
        float n0 = 0.f, n1 = 0.f;
        if (valid && t + 2 < T) {
            const float* pg = gx + (size_t)(t+2)*G1;
            n0 = pg[r0]; n1 = pg[r1];
        }
        const ulonglong2* h8 = (const ulonglong2*)h_sh[buf];
        u64 a0 = pk(g00, 0.f), a1 = pk(0.f,0.f);
        u64 a2 = pk(g01, 0.f), a3 = pk(0.f,0.f);
        #pragma unroll
        for (int kk = 0; kk < 8; kk++) {
            ulonglong2 hv = h8[kk];
            a0 = ffma2(wp0[2*kk    ], hv.x, a0);
            a1 = ffma2(wp0[2*kk + 1], hv.y, a1);
            a2 = ffma2(wp1[2*kk    ], hv.x, a2);
            a3 = ffma2(wp1[2*kk + 1], hv.y, a3);
        }
        float x0,x1,x2,x3,y0,y1,y2,y3;
        upk(a0,x0,x1); upk(a1,x2,x3); upk(a2,y0,y1); upk(a3,y2,y3);
        float d0 = (x0+x1) + (x2+x3);
        float d1 = (y0+y1) + (y2+y3);

        float A0 = fmaf(m0,  tanh_ap(s0*d0), b0);     // i or g
        float A1 = fmaf(0.5f, tanh_ap(0.5f*d1), 0.5f); // f or o
        float B0 = __shfl_xor_sync(0xFFFFFFFFu, A0, 1);
        float B1 = __shfl_xor_sync(0xFFFFFFFFu, A1, 1);

        float I = p ? B0 : A0;
        float F = p ? B1 : A1;
        float G = p ? A0 : B0;
        float O = p ? A1 : B1;
        c = fmaf(F, c, I*G);
        float hn = O * tanh_ap(c);
        if (p == 0 && valid) {
            h_sh[buf^1][u] = hn;
            g_l1[(size_t)t*D2 + off + u] = hn;
        }
        __syncthreads();
        buf ^= 1;
        g00 = g10; g01 = g11; g10 = n0; g11 = n1;
    }
}

// ============================================================
// Kernel 3: layer-2 input projections (transposed W in shared).
// ============================================================
#define GX2_BLOCKS 64
__global__ void __launch_bounds__(256) k_gx2(
    const float* __restrict__ WihF, const float* __restrict__ bF,
    const float* __restrict__ WihB, const float* __restrict__ bB) {
    __shared__ float W[D2 * G2];   // [k][j]
    __shared__ float row[D2];
    const bool bw = (blockIdx.y == 1);
    const float* Wih = bw ? WihB : WihF;
    const float* b   = bw ? bB   : bF;
    float* dst = bw ? g_gx_bw2 : g_gx_fw2;

    for (int i = threadIdx.x; i < G2*D2; i += blockDim.x) {
        int r = i / D2, k = i % D2;
        W[k*G2 + r] = Wih[i];
    }
    float bias = (threadIdx.x < G2) ? b[threadIdx.x] : 0.f;
    __syncthreads();

    const int tpb = T / GX2_BLOCKS;
    const int t0 = blockIdx.x * tpb;
    for (int t = t0; t < t0 + tpb; t++) {
        int src = bw ? (T-1-t) : t;
        __syncthreads();
        for (int i = threadIdx.x; i < D2; i += blockDim.x) row[i] = g_l1[(size_t)src*D2 + i];
        __syncthreads();
        if (threadIdx.x < G2) {
            float acc = bias;
            #pragma unroll
            for (int k = 0; k < D2; k++) acc += W[k*G2 + threadIdx.x] * row[k];
            dst[(size_t)t*G2 + threadIdx.x] = acc;
        }
    }
}

// ============================================================
// Kernel 4: layer-2 scan, same (unit, gate-pair) structure.
// 128 threads (u<50 valid), one barrier per step.
// ============================================================
__global__ void __launch_bounds__(128, 1) k_scan2(
    const float* __restrict__ WhhF, const float* __restrict__ h0F, const float* __restrict__ c0F,
    const float* __restrict__ WhhB, const float* __restrict__ h0B, const float* __restrict__ c0B) {
    const bool bw = (blockIdx.x == 1);
    const float* Whh = bw ? WhhB : WhhF;
    const float* h0  = bw ? h0B  : h0F;
    const float* c0  = bw ? c0B  : c0F;
    const float* gx  = bw ? g_gx_bw2 : g_gx_fw2;
    const int off = bw ? H2 : 0;

    __shared__ __align__(16) float h_sh[2][56];   // 52 used, 16B-aligned rows

    const int tid = threadIdx.x;
    const int u = tid >> 1;
    const int p = tid & 1;
    const bool valid = (u < H2);
    const int uu = valid ? u : 0;
    const int r0 = p ? (2*H2 + uu) : uu;          // i or g
    const int r1 = p ? (3*H2 + uu) : (H2 + uu);   // f or o

    u64 wp0[26], wp1[26];
    #pragma unroll
    for (int k = 0; k < 25; k++) {
        wp0[k] = pk(valid ? Whh[r0*H2 + 2*k] : 0.f, valid ? Whh[r0*H2 + 2*k + 1] : 0.f);
        wp1[k] = pk(valid ? Whh[r1*H2 + 2*k] : 0.f, valid ? Whh[r1*H2 + 2*k + 1] : 0.f);
    }
    wp0[25] = pk(0.f, 0.f);
    wp1[25] = pk(0.f, 0.f);

    const float s0 = p ? 1.f : 0.5f;
    const float m0 = s0;
    const float b0 = p ? 0.f : 0.5f;

    if (tid < 56) {
        h_sh[0][tid] = (tid < H2) ? h0[tid] : 0.f;
        h_sh[1][tid] = 0.f;
    }
    float c = valid ? c0[uu] : 0.f;

    float g00 = valid ? gx[r0] : 0.f;
    float g01 = valid ? gx[r1] : 0.f;
    float g10 = 0.f, g11 = 0.f;
    if (valid) { const float* pg = gx + G2; g10 = pg[r0]; g11 = pg[r1]; }
    __syncthreads();

    int buf = 0;
    for (int t = 0; t < T; t++) {
        float n0 = 0.f, n1 = 0.f;
        if (valid && t + 2 < T) {
            const float* pg = gx + (size_t)(t+2)*G2;
            n0 = pg[r0]; n1 = pg[r1];
        }
        const ulonglong2* h8 = (const ulonglong2*)h_sh[buf];
        u64 a0 = pk(g00, 0.f), a1 = pk(0.f,0.f);
        u64 a2 = pk(g01, 0.f), a3 = pk(0.f,0.f);
        #pragma unroll
        for (int kk = 0; kk < 13; kk++) {
            ulonglong2 hv = h8[kk];
            a0 = ffma2(wp0[2*kk    ], hv.x, a0);
            a1 = ffma2(wp0[2*kk + 1], hv.y, a1);
            a2 = ffma2(wp1[2*kk    ], hv.x, a2);
            a3 = ffma2(wp1[2*kk + 1], hv.y, a3);
        }
        float x0,x1,x2,x3,y0,y1,y2,y3;
        upk(a0,x0,x1); upk(a1,x2,x3); upk(a2,y0,y1); upk(a3,y2,y3);
        float d0 = (x0+x1) + (x2+x3);
        float d1 = (y0+y1) + (y2+y3);

        float A0 = fmaf(m0,  tanh_ap(s0*d0), b0);
        float A1 = fmaf(0.5f, tanh_ap(0.5f*d1), 0.5f);
        float B0 = __shfl_xor_sync(0xFFFFFFFFu, A0, 1);
        float B1 = __shfl_xor_sync(0xFFFFFFFFu, A1, 1);

        float I = p ? B0 : A0;
        float F = p ? B1 : A1;
        float G = p ? A0 : B0;
        float O = p ? A1 : B1;
        c = fmaf(F, c, I*G);
        float hn = O * tanh_ap(c);
        if (p == 0 && valid) {
            h_sh[buf^1][u] = hn;
            g_l2[(size_t)t*D3 + off + u] = hn;
        }
        __syncthreads();
        buf ^= 1;
        g00 = g10; g01 = g11; g10 = n0; g11 = n1;
    }
}

// ============================================================
// Kernel 5: final MLP (weights in dynamic shared).
// ============================================================
#define MLP_SMEM ((HL*D3 + NT*HL + D3 + HL) * 4)
__global__ void __launch_bounds__(320, 1) k_mlp(
    const float* __restrict__ W1, const float* __restrict__ b1,
    const float* __restrict__ W2, const float* __restrict__ b2,
    float* __restrict__ out) {
    extern __shared__ float sm[];
    float* W1s  = sm;
    float* W2s  = W1s + HL*D3;
    float* rowS = W2s + NT*HL;
    float* hidS = rowS + D3;

    int tid = threadIdx.x;
    for (int i = tid; i < HL*D3; i += blockDim.x) W1s[i] = W1[i];
    for (int i = tid; i < NT*HL; i += blockDim.x) W2s[i] = W2[i];
    __syncthreads();

    for (int t = blockIdx.x; t < T; t += gridDim.x) {
        if (tid < D3) rowS[tid] = g_l2[(size_t)t*D3 + tid];
        __syncthreads();
        if (tid < HL) {
            float acc = b1[tid];
            const float4* wr = (const float4*)(W1s + tid*D3);
            const float4* r4 = (const float4*)rowS;
            #pragma unroll
            for (int k = 0; k < D3/4; k++) {
                float4 wv = wr[k]; float4 rv = r4[k];
                acc += wv.x*rv.x + wv.y*rv.y + wv.z*rv.z + wv.w*rv.w;
            }
            hidS[tid] = tanhf(acc);
        }
        __syncthreads();
        if (tid < NT) {
            float acc = b2[tid];
            const float4* wr = (const float4*)(W2s + tid*HL);
            const float4* h4 = (const float4*)hidS;
            #pragma unroll
            for (int k = 0; k < HL/4; k++) {
                float4 wv = wr[k]; float4 hv = h4[k];
                acc += wv.x*hv.x + wv.y*hv.y + wv.z*hv.z + wv.w*hv.w;
            }
            out[(size_t)t*NT + tid] = acc;
        }
        __syncthreads();
    }
}

// ============================================================
// launch
// ============================================================
extern "C" void kernel_launch(void* const* d_in, const int* in_sizes, int n_in,
                              void* d_out, int out_size) {
    const int*   x   = (const int*)  d_in[0];
    const float* emb = (const float*)d_in[1];

    const float* fw1_Wih = (const float*)d_in[2];
    const float* fw1_Whh = (const float*)d_in[3];
    const float* fw1_b   = (const float*)d_in[4];
    const float* fw1_h0  = (const float*)d_in[5];
    const float* fw1_c0  = (const float*)d_in[6];

    const float* bw1_Wih = (const float*)d_in[7];
    const float* bw1_Whh = (const float*)d_in[8];
    const float* bw1_b   = (const float*)d_in[9];
    const float* bw1_h0  = (const float*)d_in[10];
    const float* bw1_c0  = (const float*)d_in[11];

    const float* fw2_Wih = (const float*)d_in[12];
    const float* fw2_Whh = (const float*)d_in[13];
    const float* fw2_b   = (const float*)d_in[14];
    const float* fw2_h0  = (const float*)d_in[15];
    const float* fw2_c0  = (const float*)d_in[16];

    const float* bw2_Wih = (const float*)d_in[17];
    const float* bw2_Whh = (const float*)d_in[18];
    const float* bw2_b   = (const float*)d_in[19];
    const float* bw2_h0  = (const float*)d_in[20];
    const float* bw2_c0  = (const float*)d_in[21];

    const float* lin1_W = (const float*)d_in[22];
    const float* lin1_b = (const float*)d_in[23];
    const float* lin2_W = (const float*)d_in[24];
    const float* lin2_b = (const float*)d_in[25];

    cudaFuncSetAttribute(k_mlp, cudaFuncAttributeMaxDynamicSharedMemorySize, MLP_SMEM);

    k_gx1<<<T, 128>>>(x, emb, fw1_Wih, fw1_b, bw1_Wih, bw1_b);
    k_scan1<<<2, 64>>>(fw1_Whh, fw1_h0, fw1_c0, bw1_Whh, bw1_h0, bw1_c0);
    k_gx2<<<dim3(GX2_BLOCKS, 2), 256>>>(fw2_Wih, fw2_b, bw2_Wih, bw2_b);
    k_scan2<<<2, 128>>>(fw2_Whh, fw2_h0, fw2_c0, bw2_Whh, bw2_h0, bw2_c0);
    k_mlp<<<148, 320, MLP_SMEM>>>(lin1_W, lin1_b, lin2_W, lin2_b, (float*)d_out);
}

// round 6
// speedup vs baseline: 1.7885x; 1.0128x over previous
#include <cuda_runtime.h>
#include <cuda_bf16.h>
#include <math.h>

#define T  8192
#define E  20
#define H1 30
#define H2 50
#define HL 300
#define NT 50
#define G1 (4*H1)   // 120
#define G2 (4*H2)   // 200
#define D2 (2*H1)   // 60
#define D3 (2*H2)   // 100

// ---- scratch (no allocations allowed) ----
__device__ float g_gx_fw1[T*G1];
__device__ float g_gx_bw1[T*G1];
__device__ float g_l1[T*D2];
__device__ float g_gx_fw2[T*G2];
__device__ float g_gx_bw2[T*G2];
__device__ float g_l2[T*D3];

typedef unsigned long long u64;

// ---- packed f32x2 + fast-activation helpers ----
__device__ __forceinline__ u64 pk(float lo, float hi) {
    u64 r; asm("mov.b64 %0, {%1, %2};" : "=l"(r) : "f"(lo), "f"(hi)); return r;
}
__device__ __forceinline__ void upk(u64 v, float& lo, float& hi) {
    asm("mov.b64 {%0, %1}, %2;" : "=f"(lo), "=f"(hi) : "l"(v));
}
__device__ __forceinline__ u64 ffma2(u64 a, u64 b, u64 c) {
    u64 d; asm("fma.rn.f32x2 %0, %1, %2, %3;" : "=l"(d) : "l"(a), "l"(b), "l"(c)); return d;
}
__device__ __forceinline__ u64 addx2(u64 a, u64 b) {
    u64 d; asm("add.rn.f32x2 %0, %1, %2;" : "=l"(d) : "l"(a), "l"(b)); return d;
}
__device__ __forceinline__ float tanh_ap(float x) {
    float y; asm("tanh.approx.f32 %0, %1;" : "=f"(y) : "f"(x)); return y;
}

// One LSTM step for the (unit, gate-pair) layout.
// Reads h from HR (ulonglong2-aligned), writes new h to HW.
// 4 accumulators per dot (short FFMA2 chain) + packed add reduction.
// Uses outer-scope: p, u, valid, c, s0, m0, b0c, Z, OUTP (advanced by OUTSTRIDE).
#define LSTM_STEP(HR, HW, GC0, GC1, NHALF, WP0, WP1, OUTP, OUTSTRIDE) do {            \
    const ulonglong2* _h8 = (const ulonglong2*)(HR);                                   \
    u64 _a0 = pk((GC0), 0.f), _a1 = Z, _a2 = Z, _a3 = Z;                               \
    u64 _b0 = pk((GC1), 0.f), _b1 = Z, _b2 = Z, _b3 = Z;                               \
    _Pragma("unroll")                                                                  \
    for (int _kk = 0; _kk < (NHALF); _kk++) {                                          \
        ulonglong2 _hv = _h8[_kk];                                                     \
        if ((_kk & 1) == 0) {                                                          \
            _a0 = ffma2((WP0)[2*_kk],   _hv.x, _a0);                                   \
            _a1 = ffma2((WP0)[2*_kk+1], _hv.y, _a1);                                   \
            _b0 = ffma2((WP1)[2*_kk],   _hv.x, _b0);                                   \
            _b1 = ffma2((WP1)[2*_kk+1], _hv.y, _b1);                                   \
        } else {                                                                       \
            _a2 = ffma2((WP0)[2*_kk],   _hv.x, _a2);                                   \
            _a3 = ffma2((WP0)[2*_kk+1], _hv.y, _a3);                                   \
            _b2 = ffma2((WP1)[2*_kk],   _hv.x, _b2);                                   \
            _b3 = ffma2((WP1)[2*_kk+1], _hv.y, _b3);                                   \
        }                                                                              \
    }                                                                                  \
    u64 _sa = addx2(addx2(_a0, _a1), addx2(_a2, _a3));                                 \
    u64 _sb = addx2(addx2(_b0, _b1), addx2(_b2, _b3));                                 \
    float _d0l,_d0h,_d1l,_d1h; upk(_sa,_d0l,_d0h); upk(_sb,_d1l,_d1h);                 \
    float _d0 = _d0l + _d0h, _d1 = _d1l + _d1h;                                        \
    float _A0 = fmaf(m0,   tanh_ap(s0*_d0),   b0c);                                    \
    float _A1 = fmaf(0.5f, tanh_ap(0.5f*_d1), 0.5f);                                   \
    float _B0 = __shfl_xor_sync(0xFFFFFFFFu, _A0, 1);                                  \
    float _B1 = __shfl_xor_sync(0xFFFFFFFFu, _A1, 1);                                  \
    float _I = p ? _B0 : _A0;                                                          \
    float _F = p ? _B1 : _A1;                                                          \
    float _G = p ? _A0 : _B0;                                                          \
    float _O = p ? _A1 : _B1;                                                          \
    c = fmaf(_F, c, _I*_G);                                                            \
    float _hn = _O * tanh_ap(c);                                                       \
    if (valid) {                                                                       \
        if (p == 0) (HW)[u] = _hn;                                                     \
        else        *(OUTP) = _hn;                                                     \
    }                                                                                  \
    (OUTP) += (OUTSTRIDE);                                                             \
    __syncthreads();                                                                   \
} while (0)

// ============================================================
// Kernel 1: embedding gather + layer-1 input projections.
// ============================================================
__global__ void k_gx1(const int* __restrict__ x, const float* __restrict__ emb,
                      const float* __restrict__ WihF, const float* __restrict__ bF,
                      const float* __restrict__ WihB, const float* __restrict__ bB) {
    __shared__ float e[E];
    int t = blockIdx.x;
    int j = threadIdx.x;
    if (j < E) e[j] = emb[(size_t)x[t] * E + j];
    __syncthreads();
    if (j < G1) {
        float aF = bF[j], aB = bB[j];
        #pragma unroll
        for (int k = 0; k < E; k++) {
            float ev = e[k];
            aF += WihF[j*E + k] * ev;
            aB += WihB[j*E + k] * ev;
        }
        g_gx_fw1[t*G1 + j] = aF;
        g_gx_bw1[(T-1-t)*G1 + j] = aB;
    }
}

// ============================================================
// Kernel 2: layer-1 scan, (unit, gate-pair) layout, unroll-2
// with hard-coded ping-pong buffers + pointer increments.
// ============================================================
__global__ void __launch_bounds__(64, 1) k_scan1(
    const float* __restrict__ WhhF, const float* __restrict__ h0F, const float* __restrict__ c0F,
    const float* __restrict__ WhhB, const float* __restrict__ h0B, const float* __restrict__ c0B) {
    const bool bw = (blockIdx.x == 1);
    const float* Whh = bw ? WhhB : WhhF;
    const float* h0  = bw ? h0B  : h0F;
    const float* c0  = bw ? c0B  : c0F;
    const float* gx  = bw ? g_gx_bw1 : g_gx_fw1;
    const int off = bw ? H1 : 0;

    __shared__ __align__(16) float h_sh[2][32];

    const int tid = threadIdx.x;
    const int u = tid >> 1;
    const int p = tid & 1;
    const bool valid = (u < H1);
    const int uu = valid ? u : 0;
    const int r0 = p ? (2*H1 + uu) : uu;          // i or g
    const int r1 = p ? (3*H1 + uu) : (H1 + uu);   // f or o

    u64 wp0[16], wp1[16];
    #pragma unroll
    for (int k = 0; k < 15; k++) {
        wp0[k] = pk(valid ? Whh[r0*H1 + 2*k] : 0.f, valid ? Whh[r0*H1 + 2*k + 1] : 0.f);
        wp1[k] = pk(valid ? Whh[r1*H1 + 2*k] : 0.f, valid ? Whh[r1*H1 + 2*k + 1] : 0.f);
    }
    wp0[15] = pk(0.f, 0.f);
    wp1[15] = pk(0.f, 0.f);

    const float s0  = p ? 1.f : 0.5f;
    const float m0  = s0;
    const float b0c = p ? 0.f : 0.5f;
    const u64 Z = pk(0.f, 0.f);

    if (tid < 32) {
        h_sh[0][tid] = (tid < H1) ? h0[tid] : 0.f;
        h_sh[1][tid] = 0.f;
    }
    float c = valid ? c0[uu] : 0.f;

    float ga0 = valid ? gx[r0]      : 0.f;
    float ga1 = valid ? gx[r1]      : 0.f;
    float gb0 = valid ? gx[G1 + r0] : 0.f;
    float gb1 = valid ? gx[G1 + r1] : 0.f;
    const float* pre = gx + 2*G1;
    float* outp = g_l1 + off + uu;
    __syncthreads();

    for (int t = 0; t < T - 2; t += 2) {
        {
            float gc0 = ga0, gc1 = ga1;
            if (valid) { ga0 = pre[r0]; ga1 = pre[r1]; }
            pre += G1;
            LSTM_STEP(h_sh[0], h_sh[1], gc0, gc1, 8, wp0, wp1, outp, D2);
        }
        {
            float gc0 = gb0, gc1 = gb1;
            if (valid) { gb0 = pre[r0]; gb1 = pre[r1]; }
            pre += G1;
            LSTM_STEP(h_sh[1], h_sh[0], gc0, gc1, 8, wp0, wp1, outp, D2);
        }
    }
    LSTM_STEP(h_sh[0], h_sh[1], ga0, ga1, 8, wp0, wp1, outp, D2);
    LSTM_STEP(h_sh[1], h_sh[0], gb0, gb1, 8, wp0, wp1, outp, D2);
}

// ============================================================
// Kernel 3: layer-2 input projections (transposed W in shared).
// ============================================================
#define GX2_BLOCKS 64
__global__ void __launch_bounds__(256) k_gx2(
    const float* __restrict__ WihF, const float* __restrict__ bF,
    const float* __restrict__ WihB, const float* __restrict__ bB) {
    __shared__ float W[D2 * G2];   // [k][j]
    __shared__ float row[D2];
    const bool bw = (blockIdx.y == 1);
    const float* Wih = bw ? WihB : WihF;
    const float* b   = bw ? bB   : bF;
    float* dst = bw ? g_gx_bw2 : g_gx_fw2;

    for (int i = threadIdx.x; i < G2*D2; i += blockDim.x) {
        int r = i / D2, k = i % D2;
        W[k*G2 + r] = Wih[i];
    }
    float bias = (threadIdx.x < G2) ? b[threadIdx.x] : 0.f;
    __syncthreads();

    const int tpb = T / GX2_BLOCKS;
    const int t0 = blockIdx.x * tpb;
    for (int t = t0; t < t0 + tpb; t++) {
        int src = bw ? (T-1-t) : t;
        __syncthreads();
        for (int i = threadIdx.x; i < D2; i += blockDim.x) row[i] = g_l1[(size_t)src*D2 + i];
        __syncthreads();
        if (threadIdx.x < G2) {
            float acc = bias;
            #pragma unroll
            for (int k = 0; k < D2; k++) acc += W[k*G2 + threadIdx.x] * row[k];
            dst[(size_t)t*G2 + threadIdx.x] = acc;
        }
    }
}

// ============================================================
// Kernel 4: layer-2 scan, same structure (13 ulonglong2 halves).
// ============================================================
__global__ void __launch_bounds__(128, 1) k_scan2(
    const float* __restrict__ WhhF, const float* __restrict__ h0F, const float* __restrict__ c0F,
    const float* __restrict__ WhhB, const float* __restrict__ h0B, const float* __restrict__ c0B) {
    const bool bw = (blockIdx.x == 1);
    const float* Whh = bw ? WhhB : WhhF;
    const float* h0  = bw ? h0B  : h0F;
    const float* c0  = bw ? c0B  : c0F;
    const float* gx  = bw ? g_gx_bw2 : g_gx_fw2;
    const int off = bw ? H2 : 0;

    __shared__ __align__(16) float h_sh[2][56];   // 52 used per row

    const int tid = threadIdx.x;
    const int u = tid >> 1;
    const int p = tid & 1;
    const bool valid = (u < H2);
    const int uu = valid ? u : 0;
    const int r0 = p ? (2*H2 + uu) : uu;          // i or g
    const int r1 = p ? (3*H2 + uu) : (H2 + uu);   // f or o

    u64 wp0[26], wp1[26];
    #pragma unroll
    for (int k = 0; k < 25; k++) {
        wp0[k] = pk(valid ? Whh[r0*H2 + 2*k] : 0.f, valid ? Whh[r0*H2 + 2*k + 1] : 0.f);
        wp1[k] = pk(valid ? Whh[r1*H2 + 2*k] : 0.f, valid ? Whh[r1*H2 + 2*k + 1] : 0.f);
    }
    wp0[25] = pk(0.f, 0.f);
    wp1[25] = pk(0.f, 0.f);

    const float s0  = p ? 1.f : 0.5f;
    const float m0  = s0;
    const float b0c = p ? 0.f : 0.5f;
    const u64 Z = pk(0.f, 0.f);

    if (tid < 56) {
        h_sh[0][tid] = (tid < H2) ? h0[tid] : 0.f;
        h_sh[1][tid] = 0.f;
    }
    float c = valid ? c0[uu] : 0.f;

    float ga0 = valid ? gx[r0]      : 0.f;
    float ga1 = valid ? gx[r1]      : 0.f;
    float gb0 = valid ? gx[G2 + r0] : 0.f;
    float gb1 = valid ? gx[G2 + r1] : 0.f;
    const float* pre = gx + 2*G2;
    float* outp = g_l2 + off + uu;
    __syncthreads();

    for (int t = 0; t < T - 2; t += 2) {
        {
            float gc0 = ga0, gc1 = ga1;
            if (valid) { ga0 = pre[r0]; ga1 = pre[r1]; }
            pre += G2;
            LSTM_STEP(h_sh[0], h_sh[1], gc0, gc1, 13, wp0, wp1, outp, D3);
        }
        {
            float gc0 = gb0, gc1 = gb1;
            if (valid) { gb0 = pre[r0]; gb1 = pre[r1]; }
            pre += G2;
            LSTM_STEP(h_sh[1], h_sh[0], gc0, gc1, 13, wp0, wp1, outp, D3);
        }
    }
    LSTM_STEP(h_sh[0], h_sh[1], ga0, ga1, 13, wp0, wp1, outp, D3);
    LSTM_STEP(h_sh[1], h_sh[0], gb0, gb1, 13, wp0, wp1, outp, D3);
}

// ============================================================
// Kernel 5: final MLP (weights in dynamic shared).
// ============================================================
#define MLP_SMEM ((HL*D3 + NT*HL + D3 + HL) * 4)
__global__ void __launch_bounds__(320, 1) k_mlp(
    const float* __restrict__ W1, const float* __restrict__ b1,
    const float* __restrict__ W2, const float* __restrict__ b2,
    float* __restrict__ out) {
    extern __shared__ float sm[];
    float* W1s  = sm;
    float* W2s  = W1s + HL*D3;
    float* rowS = W2s + NT*HL;
    float* hidS = rowS + D3;

    int tid = threadIdx.x;
    for (int i = tid; i < HL*D3; i += blockDim.x) W1s[i] = W1[i];
    for (int i = tid; i < NT*HL; i += blockDim.x) W2s[i] = W2[i];
    __syncthreads();

    for (int t = blockIdx.x; t < T; t += gridDim.x) {
        if (tid < D3) rowS[tid] = g_l2[(size_t)t*D3 + tid];
        __syncthreads();
        if (tid < HL) {
            float acc = b1[tid];
            const float4* wr = (const float4*)(W1s + tid*D3);
            const float4* r4 = (const float4*)rowS;
            #pragma unroll
            for (int k = 0; k < D3/4; k++) {
                float4 wv = wr[k]; float4 rv = r4[k];
                acc += wv.x*rv.x + wv.y*rv.y + wv.z*rv.z + wv.w*rv.w;
            }
            hidS[tid] = tanhf(acc);
        }
        __syncthreads();
        if (tid < NT) {
            float acc = b2[tid];
            const float4* wr = (const float4*)(W2s + tid*HL);
            const float4* h4 = (const float4*)hidS;
            #pragma unroll
            for (int k = 0; k < HL/4; k++) {
                float4 wv = wr[k]; float4 hv = h4[k];
                acc += wv.x*hv.x + wv.y*hv.y + wv.z*hv.z + wv.w*hv.w;
            }
            out[(size_t)t*NT + tid] = acc;
        }
        __syncthreads();
    }
}

// ============================================================
// launch
// ============================================================
extern "C" void kernel_launch(void* const* d_in, const int* in_sizes, int n_in,
                              void* d_out, int out_size) {
    const int*   x   = (const int*)  d_in[0];
    const float* emb = (const float*)d_in[1];

    const float* fw1_Wih = (const float*)d_in[2];
    const float* fw1_Whh = (const float*)d_in[3];
    const float* fw1_b   = (const float*)d_in[4];
    const float* fw1_h0  = (const float*)d_in[5];
    const float* fw1_c0  = (const float*)d_in[6];

    const float* bw1_Wih = (const float*)d_in[7];
    const float* bw1_Whh = (const float*)d_in[8];
    const float* bw1_b   = (const float*)d_in[9];
    const float* bw1_h0  = (const float*)d_in[10];
    const float* bw1_c0  = (const float*)d_in[11];

    const float* fw2_Wih = (const float*)d_in[12];
    const float* fw2_Whh = (const float*)d_in[13];
    const float* fw2_b   = (const float*)d_in[14];
    const float* fw2_h0  = (const float*)d_in[15];
    const float* fw2_c0  = (const float*)d_in[16];

    const float* bw2_Wih = (const float*)d_in[17];
    const float* bw2_Whh = (const float*)d_in[18];
    const float* bw2_b   = (const float*)d_in[19];
    const float* bw2_h0  = (const float*)d_in[20];
    const float* bw2_c0  = (const float*)d_in[21];

    const float* lin1_W = (const float*)d_in[22];
    const float* lin1_b = (const float*)d_in[23];
    const float* lin2_W = (const float*)d_in[24];
    const float* lin2_b = (const float*)d_in[25];

    cudaFuncSetAttribute(k_mlp, cudaFuncAttributeMaxDynamicSharedMemorySize, MLP_SMEM);

    k_gx1<<<T, 128>>>(x, emb, fw1_Wih, fw1_b, bw1_Wih, bw1_b);
    k_scan1<<<2, 64>>>(fw1_Whh, fw1_h0, fw1_c0, bw1_Whh, bw1_h0, bw1_c0);
    k_gx2<<<dim3(GX2_BLOCKS, 2), 256>>>(fw2_Wih, fw2_b, bw2_Wih, bw2_b);
    k_scan2<<<2, 128>>>(fw2_Whh, fw2_h0, fw2_c0, bw2_Whh, bw2_h0, bw2_c0);
    k_mlp<<<148, 320, MLP_SMEM>>>(lin1_W, lin1_b, lin2_W, lin2_b, (float*)d_out);
}